// round 1
// baseline (speedup 1.0000x reference)
#include <cuda_runtime.h>

#define BB   32
#define CCH  256
#define HH   56
#define HWW  3136      // 56*56
#define HP   58        // padded spatial
#define PTOT 100352    // BB*HWW
#define WSZ  589824    // 256*256*9

// ---------------- device scratch (zero-initialized .bss) ----------------
__device__ __align__(16) float g_tpad[BB * HP * HP * CCH]; // padded NHWC activations (borders stay 0)
__device__ __align__(16) float g_out1[PTOT * CCH];         // conv1 output, NHWC
__device__ __align__(16) float g_qw0[9 * CCH * CCH];       // E0*sign(w0), [k][ci][co]
__device__ __align__(16) float g_qw1[9 * CCH * CCH];       // E1*sign(w1), [k][ci][co]
__device__ float g_scale0[CCH], g_shift0[CCH];
__device__ float g_scale1[CCH], g_shift1[CCH];
__device__ float g_epart[128];
__device__ float g_E[2];
__device__ float g_ps[98 * CCH], g_pq[98 * CCH];

// ---------------- BN0 stats: one block per channel ----------------
__global__ void stats0_kernel(const float* __restrict__ x,
                              const float* __restrict__ gamma,
                              const float* __restrict__ beta)
{
    int c = blockIdx.x;
    int t = threadIdx.x;
    float s = 0.f, q = 0.f;
    for (int n = 0; n < BB; ++n) {
        const float* base = x + ((size_t)n * CCH + c) * HWW;
        for (int i = t; i < HWW; i += 256) {
            float v = base[i];
            s += v; q += v * v;
        }
    }
    __shared__ float ss[256], sq[256];
    ss[t] = s; sq[t] = q; __syncthreads();
    for (int o = 128; o > 0; o >>= 1) {
        if (t < o) { ss[t] += ss[t + o]; sq[t] += sq[t + o]; }
        __syncthreads();
    }
    if (t == 0) {
        float m   = ss[0] / (float)PTOT;
        float var = sq[0] / (float)PTOT - m * m;
        float sc  = gamma[c] * rsqrtf(var + 1e-5f);
        g_scale0[c] = sc;
        g_shift0[c] = beta[c] - m * sc;
    }
}

// ---------------- E = mean(|w|): partials then tiny finalize ----------------
__global__ void eabs_part(const float* __restrict__ w0, const float* __restrict__ w1)
{
    int b = blockIdx.x;
    const float* w = (b < 64) ? w0 : w1;
    int bl = b & 63;
    int t = threadIdx.x;
    float s = 0.f;
    for (int i = bl * 256 + t; i < WSZ; i += 64 * 256) s += fabsf(w[i]);
    __shared__ float ss[256];
    ss[t] = s; __syncthreads();
    for (int o = 128; o > 0; o >>= 1) { if (t < o) ss[t] += ss[t + o]; __syncthreads(); }
    if (t == 0) g_epart[b] = ss[0];
}

__global__ void eabs_final()
{
    int t = threadIdx.x;
    if (t == 0) { float a = 0.f; for (int i = 0;  i < 64;  ++i) a += g_epart[i]; g_E[0] = a / (float)WSZ; }
    if (t == 1) { float a = 0.f; for (int i = 64; i < 128; ++i) a += g_epart[i]; g_E[1] = a / (float)WSZ; }
}

// ---------------- build E*sign(w) in [k][ci][co] layout ----------------
__global__ void quantw_kernel(const float* __restrict__ w0, const float* __restrict__ w1)
{
    int idx = blockIdx.x * 256 + threadIdx.x;       // 0 .. 2*WSZ
    int which = (idx >= WSZ) ? 1 : 0;
    int o = idx - which * WSZ;
    const float* w = which ? w1 : w0;
    float* qw = which ? g_qw1 : g_qw0;
    float E = g_E[which];
    int co = o & 255;
    int ci = (o >> 8) & 255;
    int k  = o >> 16;                                // 0..8
    float v = w[co * 2304 + ci * 9 + k];             // OIHW source
    qw[o] = (v > 0.f) ? E : ((v < 0.f) ? -E : 0.f);
}

// ---------------- BN0 + ReLU: NCHW -> padded NHWC (smem transpose) ----------------
__global__ void bnrelu0_kernel(const float* __restrict__ x)
{
    __shared__ float sm[128][57];
    int h = blockIdx.x, n = blockIdx.y, cc = blockIdx.z;  // cc: channel half
    int t = threadIdx.x;
    #pragma unroll
    for (int it = 0; it < 28; ++it) {                 // 128*56/256
        int idx = it * 256 + t;
        int cl = idx / 56, w = idx - cl * 56;
        sm[cl][w] = x[((size_t)(n * CCH + cc * 128 + cl)) * HWW + h * HH + w];
    }
    __syncthreads();
    int base = ((n * HP + h + 1) * HP + 1) * CCH + cc * 128;
    #pragma unroll
    for (int it = 0; it < 28; ++it) {
        int idx = it * 256 + t;
        int w = idx >> 7, cl = idx & 127;
        int c = cc * 128 + cl;
        float v = sm[cl][w] * g_scale0[c] + g_shift0[c];
        g_tpad[base + w * CCH + cl] = fmaxf(v, 0.f);
    }
}

// ---------------- conv3x3 as 9 shifted GEMMs (64x64 tile, 4x4 micro) ----------------
// pass 0: out = conv(g_tpad, g_qw0) -> g_out1 (NHWC)
// pass 1: dout(NCHW) = conv(g_tpad, g_qw1) + shortcut(NCHW)
__global__ void __launch_bounds__(256) conv_kernel(float* __restrict__ dout,
                                                   const float* __restrict__ shortcut,
                                                   int pass)
{
    __shared__ float As[16][64];   // [ci-in-chunk][pixel]
    __shared__ float Bs[16][64];   // [ci-in-chunk][co]
    const float* __restrict__ qw = pass ? g_qw1 : g_qw0;

    const int t   = threadIdx.x;
    const int p0  = blockIdx.x * 64;                 // pixel tile base (never crosses image: 3136%64==0)
    const int co0 = blockIdx.y * 64;
    const int n0  = p0 / HWW;
    const int s0  = p0 - n0 * HWW;

    // A loader: thread -> one pixel, 4 ci
    const int lp  = t >> 2;                          // 0..63
    const int lci = (t & 3) << 2;                    // 0,4,8,12
    const int sl  = s0 + lp;
    const int yl  = sl / HH;
    const int xl  = sl - yl * HH;
    // B loader
    const int lcib = t >> 4;                         // 0..15
    const int lco  = (t & 15) << 2;
    // compute mapping
    const int pg = (t & 15) << 2;                    // pixel offset
    const int cg = (t >> 4) << 2;                    // co offset

    float acc[4][4];
    #pragma unroll
    for (int i = 0; i < 4; ++i)
        #pragma unroll
        for (int j = 0; j < 4; ++j) acc[i][j] = 0.f;

    float4 aR, bR;
    {   // prefetch m = 0 (kk=0: kh=0, kw=0, ci0=0)
        int abase = ((n0 * HP + yl) * HP + xl) * CCH;
        aR = *(const float4*)&g_tpad[abase + lci];
        bR = *(const float4*)&qw[lcib * CCH + co0 + lco];
    }

    for (int m = 0; m < 144; ++m) {                  // 9 taps * 16 ci-chunks
        __syncthreads();
        As[lci + 0][lp] = aR.x;
        As[lci + 1][lp] = aR.y;
        As[lci + 2][lp] = aR.z;
        As[lci + 3][lp] = aR.w;
        *(float4*)&Bs[lcib][lco] = bR;
        __syncthreads();

        if (m + 1 < 144) {                           // prefetch next chunk (latency hidden by compute)
            int m1  = m + 1;
            int kk  = m1 >> 4;
            int ci0 = (m1 & 15) << 4;
            int kh  = kk / 3;
            int kw  = kk - kh * 3;
            int abase = ((n0 * HP + yl + kh) * HP + (xl + kw)) * CCH;
            aR = *(const float4*)&g_tpad[abase + ci0 + lci];
            bR = *(const float4*)&qw[kk * 65536 + (ci0 + lcib) * CCH + co0 + lco];
        }

        #pragma unroll
        for (int kb = 0; kb < 16; ++kb) {
            float4 a = *(const float4*)&As[kb][pg];
            float4 b = *(const float4*)&Bs[kb][cg];
            acc[0][0] += a.x * b.x; acc[0][1] += a.x * b.y; acc[0][2] += a.x * b.z; acc[0][3] += a.x * b.w;
            acc[1][0] += a.y * b.x; acc[1][1] += a.y * b.y; acc[1][2] += a.y * b.z; acc[1][3] += a.y * b.w;
            acc[2][0] += a.z * b.x; acc[2][1] += a.z * b.y; acc[2][2] += a.z * b.z; acc[2][3] += a.z * b.w;
            acc[3][0] += a.w * b.x; acc[3][1] += a.w * b.y; acc[3][2] += a.w * b.z; acc[3][3] += a.w * b.w;
        }
    }

    if (pass == 0) {
        // NHWC: out1[p][co]
        #pragma unroll
        for (int i = 0; i < 4; ++i) {
            int p = p0 + pg + i;
            float4 v = make_float4(acc[i][0], acc[i][1], acc[i][2], acc[i][3]);
            *(float4*)&g_out1[(size_t)p * CCH + co0 + cg] = v;
        }
    } else {
        // NCHW + shortcut
        #pragma unroll
        for (int j = 0; j < 4; ++j) {
            int co = co0 + cg + j;
            int basei = (n0 * CCH + co) * HWW + s0 + pg;
            float4 s4 = *(const float4*)&shortcut[basei];
            float4 v = make_float4(acc[0][j] + s4.x, acc[1][j] + s4.y,
                                   acc[2][j] + s4.z, acc[3][j] + s4.w);
            *(float4*)&dout[basei] = v;
        }
    }
}

// ---------------- BN1 stats over g_out1 (NHWC): partials + finalize ----------------
__global__ void stats1_part()
{
    int b = blockIdx.x, t = threadIdx.x;
    const float* base = g_out1 + (size_t)b * 1024 * CCH;
    float s = 0.f, q = 0.f;
    for (int i = 0; i < 1024; ++i) {
        float v = base[(size_t)i * CCH + t];
        s += v; q += v * v;
    }
    g_ps[b * CCH + t] = s;
    g_pq[b * CCH + t] = q;
}

__global__ void stats1_final(const float* __restrict__ gamma, const float* __restrict__ beta)
{
    int c = threadIdx.x;
    float s = 0.f, q = 0.f;
    for (int b = 0; b < 98; ++b) { s += g_ps[b * CCH + c]; q += g_pq[b * CCH + c]; }
    float m   = s / (float)PTOT;
    float var = q / (float)PTOT - m * m;
    float sc  = gamma[c] * rsqrtf(var + 1e-5f);
    g_scale1[c] = sc;
    g_shift1[c] = beta[c] - m * sc;
}

// ---------------- BN1 + ReLU: NHWC -> padded NHWC ----------------
__global__ void bnrelu1_kernel()
{
    int p = blockIdx.x, t = threadIdx.x;
    int n = p / HWW, s = p - n * HWW;
    int y = s / HH, xw = s - y * HH;
    float v = g_out1[(size_t)p * CCH + t];
    v = fmaxf(v * g_scale1[t] + g_shift1[t], 0.f);
    g_tpad[((n * HP + y + 1) * HP + xw + 1) * CCH + t] = v;
}

// ---------------- launch ----------------
extern "C" void kernel_launch(void* const* d_in, const int* in_sizes, int n_in,
                              void* d_out, int out_size)
{
    const float* x      = (const float*)d_in[0];
    const float* gamma0 = (const float*)d_in[1];
    const float* beta0  = (const float*)d_in[2];
    const float* w0     = (const float*)d_in[3];
    const float* gamma1 = (const float*)d_in[4];
    const float* beta1  = (const float*)d_in[5];
    const float* w1     = (const float*)d_in[6];
    float* out = (float*)d_out;
    (void)in_sizes; (void)n_in; (void)out_size;

    stats0_kernel<<<256, 256>>>(x, gamma0, beta0);
    eabs_part<<<128, 256>>>(w0, w1);
    eabs_final<<<1, 32>>>();
    quantw_kernel<<<(2 * WSZ) / 256, 256>>>(w0, w1);
    bnrelu0_kernel<<<dim3(HH, BB, 2), 256>>>(x);
    conv_kernel<<<dim3(PTOT / 64, 4), 256>>>(nullptr, nullptr, 0);
    stats1_part<<<98, 256>>>();
    stats1_final<<<1, 256>>>(gamma1, beta1);
    bnrelu1_kernel<<<PTOT, 256>>>();
    conv_kernel<<<dim3(PTOT / 64, 4), 256>>>(out, x, 1);
}

// round 3
// speedup vs baseline: 4.2296x; 4.2296x over previous
#include <cuda_runtime.h>
#include <cuda_bf16.h>
#include <cstdint>

#define BB   32
#define CCH  256
#define HH   56
#define HWW  3136      // 56*56
#define HP   58        // padded spatial
#define PTOT 100352    // BB*HWW
#define WSZ  589824    // 256*256*9
#define WQN  294912    // u32 fragments per pass: 9*16*32*2*32

// ---------------- device scratch (zero-initialized .bss) ----------------
__device__ __align__(16) __nv_bfloat16 g_ahi[BB * HP * HP * CCH]; // padded NHWC act, hi plane
__device__ __align__(16) __nv_bfloat16 g_alo[BB * HP * HP * CCH]; // padded NHWC act, lo plane
__device__ __align__(16) float g_out1[(size_t)PTOT * CCH];        // conv1 output, NHWC fp32
__device__ __align__(16) uint32_t g_wq[2][WQN];                   // sign(w) bf16x2, HMMA B-fragment order
__device__ float g_scale0[CCH], g_shift0[CCH];
__device__ float g_scale1[CCH], g_shift1[CCH];
__device__ float g_epart[128];
__device__ float g_E[2];
__device__ float g_ps[98 * CCH], g_pq[98 * CCH];

// ---------------- helpers ----------------
__device__ __forceinline__ uint32_t smem_u32(const void* p) {
    uint32_t a;
    asm("{ .reg .u64 t; cvta.to.shared.u64 t, %1; cvt.u32.u64 %0, t; }" : "=r"(a) : "l"(p));
    return a;
}
#define CPA16(dst, src) \
    asm volatile("cp.async.cg.shared.global [%0], [%1], 16;" :: "r"(dst), "l"(src) : "memory")
#define CPA_COMMIT() asm volatile("cp.async.commit_group;" ::: "memory")
#define CPA_WAIT(n)  asm volatile("cp.async.wait_group %0;" :: "n"(n) : "memory")

#define LDMATRIX_X4(r0, r1, r2, r3, addr) \
    asm volatile("ldmatrix.sync.aligned.m8n8.x4.shared.b16 {%0,%1,%2,%3}, [%4];" \
        : "=r"(r0), "=r"(r1), "=r"(r2), "=r"(r3) : "r"(addr))

#define MMA16816(c, a, b0, b1) \
    asm volatile("mma.sync.aligned.m16n8k16.row.col.f32.bf16.bf16.f32 " \
        "{%0,%1,%2,%3},{%4,%5,%6,%7},{%8,%9},{%0,%1,%2,%3};" \
        : "+f"((c)[0]), "+f"((c)[1]), "+f"((c)[2]), "+f"((c)[3]) \
        : "r"((a)[0]), "r"((a)[1]), "r"((a)[2]), "r"((a)[3]), "r"(b0), "r"(b1))

// ---------------- BN0 stats: one block per channel ----------------
__global__ void stats0_kernel(const float* __restrict__ x,
                              const float* __restrict__ gamma,
                              const float* __restrict__ beta)
{
    int c = blockIdx.x;
    int t = threadIdx.x;
    float s = 0.f, q = 0.f;
    for (int n = 0; n < BB; ++n) {
        const float* base = x + ((size_t)n * CCH + c) * HWW;
        for (int i = t; i < HWW; i += 256) {
            float v = base[i];
            s += v; q += v * v;
        }
    }
    __shared__ float ss[256], sq[256];
    ss[t] = s; sq[t] = q; __syncthreads();
    for (int o = 128; o > 0; o >>= 1) {
        if (t < o) { ss[t] += ss[t + o]; sq[t] += sq[t + o]; }
        __syncthreads();
    }
    if (t == 0) {
        float m   = ss[0] / (float)PTOT;
        float var = sq[0] / (float)PTOT - m * m;
        float sc  = gamma[c] * rsqrtf(var + 1e-5f);
        g_scale0[c] = sc;
        g_shift0[c] = beta[c] - m * sc;
    }
}

// ---------------- E = mean(|w|) ----------------
__global__ void eabs_part(const float* __restrict__ w0, const float* __restrict__ w1)
{
    int b = blockIdx.x;
    const float* w = (b < 64) ? w0 : w1;
    int bl = b & 63;
    int t = threadIdx.x;
    float s = 0.f;
    for (int i = bl * 256 + t; i < WSZ; i += 64 * 256) s += fabsf(w[i]);
    __shared__ float ss[256];
    ss[t] = s; __syncthreads();
    for (int o = 128; o > 0; o >>= 1) { if (t < o) ss[t] += ss[t + o]; __syncthreads(); }
    if (t == 0) g_epart[b] = ss[0];
}

__global__ void eabs_final()
{
    int t = threadIdx.x;
    if (t == 0) { float a = 0.f; for (int i = 0;  i < 64;  ++i) a += g_epart[i]; g_E[0] = a / (float)WSZ; }
    if (t == 1) { float a = 0.f; for (int i = 64; i < 128; ++i) a += g_epart[i]; g_E[1] = a / (float)WSZ; }
}

// ---------------- build sign(w) in HMMA B-fragment order ----------------
// layout: [tap 9][kstep 16][n8 32][reg 2][lane 32] as u32 = bf16x2 over (k, k+1)
// fragment semantics: k = kstep*16 + (lane&3)*2 + reg*8 (+0/+1), n(co) = n8*8 + (lane>>2)
__global__ void quantw_kernel(const float* __restrict__ w0, const float* __restrict__ w1)
{
    int idx = blockIdx.x * 256 + threadIdx.x;        // 0 .. 2*WQN
    int which = (idx >= WQN) ? 1 : 0;
    int i = idx - which * WQN;
    const float* w = which ? w1 : w0;
    int lane = i & 31;
    int r    = (i >> 5) & 1;
    int n8   = (i >> 6) & 31;
    int kst  = (i >> 11) & 15;
    int tap  = i >> 15;                               // 0..8
    int ci = kst * 16 + (lane & 3) * 2 + r * 8;
    int co = n8 * 8 + (lane >> 2);
    float v0 = w[co * 2304 + (ci + 0) * 9 + tap];     // OIHW source
    float v1 = w[co * 2304 + (ci + 1) * 9 + tap];
    float s0 = (v0 > 0.f) ? 1.0f : ((v0 < 0.f) ? -1.0f : 0.0f);
    float s1 = (v1 > 0.f) ? 1.0f : ((v1 < 0.f) ? -1.0f : 0.0f);
    uint32_t lo = (uint32_t)__bfloat16_as_ushort(__float2bfloat16(s0));
    uint32_t hi = (uint32_t)__bfloat16_as_ushort(__float2bfloat16(s1));
    g_wq[which][i] = (hi << 16) | lo;
}

// ---------------- BN0 + ReLU: NCHW -> padded NHWC hi/lo bf16 ----------------
__global__ void bnrelu0_kernel(const float* __restrict__ x)
{
    __shared__ float sm[128][57];
    int h = blockIdx.x, n = blockIdx.y, cc = blockIdx.z;
    int t = threadIdx.x;
    #pragma unroll
    for (int it = 0; it < 28; ++it) {
        int idx = it * 256 + t;
        int cl = idx / 56, w = idx - cl * 56;
        sm[cl][w] = x[((size_t)(n * CCH + cc * 128 + cl)) * HWW + h * HH + w];
    }
    __syncthreads();
    int base = ((n * HP + h + 1) * HP + 1) * CCH + cc * 128;
    #pragma unroll
    for (int it = 0; it < 28; ++it) {
        int idx = it * 256 + t;
        int w = idx >> 7, cl = idx & 127;
        int c = cc * 128 + cl;
        float v = fmaxf(sm[cl][w] * g_scale0[c] + g_shift0[c], 0.f);
        __nv_bfloat16 hi = __float2bfloat16(v);
        __nv_bfloat16 lo = __float2bfloat16(v - __bfloat162float(hi));
        g_ahi[base + w * CCH + cl] = hi;
        g_alo[base + w * CCH + cl] = lo;
    }
}

// ---------------- conv3x3 via mma.sync bf16: CTA 128px x 128co ----------------
// K = 9 taps x 2 planes x 256 ci. 36 stages (tap x 64-ci chunk), hi+lo per stage.
// stage smem: A_hi 16KB | A_lo 16KB | B 16KB = 48KB, double-buffered.
#define STG      49152
#define SMEM_DYN (2 * STG)

__global__ void __launch_bounds__(256, 2) convmma_kernel(float* __restrict__ dout,
                                                         const float* __restrict__ shortcut,
                                                         int pass)
{
    extern __shared__ __align__(16) char cs[];
    const int t    = threadIdx.x;
    const int lane = t & 31;
    const int wid  = t >> 5;
    const int wm   = wid & 3;          // M-warp (32 px)
    const int wn   = wid >> 2;         // N-warp (64 co)
    const int p0   = blockIdx.x * 128;
    const int bn   = blockIdx.y;       // co half
    const uint32_t sbase = smem_u32(cs);
    const uint32_t* __restrict__ wq = g_wq[pass];

    // loader mapping: thread -> row lr = t>>1, 64B half lh = t&1
    const int lr = t >> 1, lh = t & 1;
    const int lp = p0 + lr;
    const int ln = lp / HWW;
    const int ls = lp - ln * HWW;
    const int ly = ls / HH;
    const int lx = ls - ly * HH;
    const uint32_t labase = ((uint32_t)(ln * HP + ly) * HP + lx) * CCH;

#define LOAD_STAGE(M_, BUF_) do { \
        int tap_ = (M_) >> 2, ch_ = (M_) & 3; \
        int kh_ = tap_ / 3, kw_ = tap_ - kh_ * 3; \
        uint32_t aoff_ = labase + (uint32_t)(kh_ * HP + kw_) * CCH + ch_ * 64; \
        const char* sh_ = (const char*)(g_ahi + aoff_); \
        const char* sl_ = (const char*)(g_alo + aoff_); \
        uint32_t rowd_ = sbase + (BUF_) * STG + (uint32_t)lr * 128; \
        _Pragma("unroll") \
        for (int g_ = 0; g_ < 4; ++g_) { \
            int gg_ = lh * 4 + g_; \
            uint32_t sw_ = (uint32_t)((gg_ ^ (lr & 7)) << 4); \
            CPA16(rowd_ + sw_,          sh_ + gg_ * 16); \
            CPA16(rowd_ + 16384 + sw_,  sl_ + gg_ * 16); \
        } \
        _Pragma("unroll") \
        for (int j_ = 0; j_ < 4; ++j_) { \
            const char* bs_ = (const char*)(wq + (size_t)(tap_ * 16 + ch_ * 4 + j_) * 2048 + bn * 1024); \
            CPA16(sbase + (BUF_) * STG + 32768 + j_ * 4096 + t * 16, bs_ + t * 16); \
        } \
        CPA_COMMIT(); \
    } while (0)

    float acc[2][8][4];
    #pragma unroll
    for (int i = 0; i < 2; ++i)
        #pragma unroll
        for (int j = 0; j < 8; ++j)
            #pragma unroll
            for (int k = 0; k < 4; ++k) acc[i][j][k] = 0.f;

    LOAD_STAGE(0, 0);

    for (int m = 0; m < 36; ++m) {
        if (m + 1 < 36) { LOAD_STAGE(m + 1, (m + 1) & 1); CPA_WAIT(1); }
        else            { CPA_WAIT(0); }
        __syncthreads();

        const uint32_t Ab = sbase + (m & 1) * STG;
        const uint32_t Bb = Ab + 32768;
        #pragma unroll
        for (int ks = 0; ks < 4; ++ks) {
            #pragma unroll
            for (int pl = 0; pl < 2; ++pl) {
                uint32_t a[2][4];
                #pragma unroll
                for (int mt = 0; mt < 2; ++mt) {
                    int row = wm * 32 + mt * 16 + (lane & 15);
                    uint32_t addr = Ab + pl * 16384 + (uint32_t)row * 128
                                  + (uint32_t)((((ks << 1) + (lane >> 4)) ^ (row & 7)) << 4);
                    LDMATRIX_X4(a[mt][0], a[mt][1], a[mt][2], a[mt][3], addr);
                }
                #pragma unroll
                for (int nt = 0; nt < 8; ++nt) {
                    int n8l = wn * 8 + nt;
                    const uint32_t* bp = (const uint32_t*)(cs + ((m & 1) * STG + 32768)
                                        + (((ks * 16 + n8l) * 2) * 32 + lane) * 4);
                    uint32_t b0 = bp[0];
                    uint32_t b1 = bp[32];
                    MMA16816(acc[0][nt], a[0], b0, b1);
                    MMA16816(acc[1][nt], a[1], b0, b1);
                }
            }
        }
        __syncthreads();
    }
    (void)0;
#undef LOAD_STAGE

    const float E = g_E[pass];

    if (pass == 0) {
        // NHWC fp32 direct fragment stores
        #pragma unroll
        for (int mt = 0; mt < 2; ++mt) {
            int row0 = p0 + wm * 32 + mt * 16 + (lane >> 2);
            #pragma unroll
            for (int nt = 0; nt < 8; ++nt) {
                int co = bn * 128 + wn * 64 + nt * 8 + (lane & 3) * 2;
                float2 v0 = make_float2(acc[mt][nt][0] * E, acc[mt][nt][1] * E);
                float2 v1 = make_float2(acc[mt][nt][2] * E, acc[mt][nt][3] * E);
                *(float2*)&g_out1[(size_t)row0 * CCH + co]       = v0;
                *(float2*)&g_out1[(size_t)(row0 + 8) * CCH + co] = v1;
            }
        }
    } else {
        // transpose through smem, then coalesced NCHW stores + shortcut
        float* tsm = (float*)cs;   // [128 co][132]
        #pragma unroll
        for (int mt = 0; mt < 2; ++mt) {
            int r0 = wm * 32 + mt * 16 + (lane >> 2);
            #pragma unroll
            for (int nt = 0; nt < 8; ++nt) {
                int c = wn * 64 + nt * 8 + (lane & 3) * 2;
                tsm[(c + 0) * 132 + r0]     = acc[mt][nt][0];
                tsm[(c + 1) * 132 + r0]     = acc[mt][nt][1];
                tsm[(c + 0) * 132 + r0 + 8] = acc[mt][nt][2];
                tsm[(c + 1) * 132 + r0 + 8] = acc[mt][nt][3];
            }
        }
        __syncthreads();
        int p = p0 + lane * 4;
        int n = p / HWW;
        int s = p - n * HWW;
        #pragma unroll
        for (int cl = 0; cl < 16; ++cl) {
            int co = wid * 16 + cl;
            size_t oi = ((size_t)(n * CCH + bn * 128 + co)) * HWW + s;
            float4 sc = *(const float4*)&shortcut[oi];
            float4 v;
            v.x = tsm[co * 132 + lane * 4 + 0] * E + sc.x;
            v.y = tsm[co * 132 + lane * 4 + 1] * E + sc.y;
            v.z = tsm[co * 132 + lane * 4 + 2] * E + sc.z;
            v.w = tsm[co * 132 + lane * 4 + 3] * E + sc.w;
            *(float4*)&dout[oi] = v;
        }
    }
}

// ---------------- BN1 stats over g_out1 (NHWC) ----------------
__global__ void stats1_part()
{
    int b = blockIdx.x, t = threadIdx.x;
    const float* base = g_out1 + (size_t)b * 1024 * CCH;
    float s = 0.f, q = 0.f;
    for (int i = 0; i < 1024; ++i) {
        float v = base[(size_t)i * CCH + t];
        s += v; q += v * v;
    }
    g_ps[b * CCH + t] = s;
    g_pq[b * CCH + t] = q;
}

__global__ void stats1_final(const float* __restrict__ gamma, const float* __restrict__ beta)
{
    int c = threadIdx.x;
    float s = 0.f, q = 0.f;
    for (int b = 0; b < 98; ++b) { s += g_ps[b * CCH + c]; q += g_pq[b * CCH + c]; }
    float m   = s / (float)PTOT;
    float var = q / (float)PTOT - m * m;
    float sc  = gamma[c] * rsqrtf(var + 1e-5f);
    g_scale1[c] = sc;
    g_shift1[c] = beta[c] - m * sc;
}

// ---------------- BN1 + ReLU: NHWC fp32 -> padded NHWC hi/lo bf16 ----------------
__global__ void bnrelu1_kernel()
{
    int p = blockIdx.x, t = threadIdx.x;
    int n = p / HWW, s = p - n * HWW;
    int y = s / HH, xw = s - y * HH;
    float v = g_out1[(size_t)p * CCH + t];
    v = fmaxf(v * g_scale1[t] + g_shift1[t], 0.f);
    __nv_bfloat16 hi = __float2bfloat16(v);
    __nv_bfloat16 lo = __float2bfloat16(v - __bfloat162float(hi));
    int o = ((n * HP + y + 1) * HP + xw + 1) * CCH + t;
    g_ahi[o] = hi;
    g_alo[o] = lo;
}

// ---------------- launch ----------------
extern "C" void kernel_launch(void* const* d_in, const int* in_sizes, int n_in,
                              void* d_out, int out_size)
{
    const float* x      = (const float*)d_in[0];
    const float* gamma0 = (const float*)d_in[1];
    const float* beta0  = (const float*)d_in[2];
    const float* w0     = (const float*)d_in[3];
    const float* gamma1 = (const float*)d_in[4];
    const float* beta1  = (const float*)d_in[5];
    const float* w1     = (const float*)d_in[6];
    float* out = (float*)d_out;
    (void)in_sizes; (void)n_in; (void)out_size;

    static int smem_set = 0;
    if (!smem_set) {
        cudaFuncSetAttribute(convmma_kernel, cudaFuncAttributeMaxDynamicSharedMemorySize, SMEM_DYN);
        smem_set = 1;
    }

    stats0_kernel<<<256, 256>>>(x, gamma0, beta0);
    eabs_part<<<128, 256>>>(w0, w1);
    eabs_final<<<1, 32>>>();
    quantw_kernel<<<(2 * WQN) / 256, 256>>>(w0, w1);
    bnrelu0_kernel<<<dim3(HH, BB, 2), 256>>>(x);
    convmma_kernel<<<dim3(PTOT / 128, 2), 256, SMEM_DYN>>>(nullptr, nullptr, 0);
    stats1_part<<<98, 256>>>();
    stats1_final<<<1, 256>>>(gamma1, beta1);
    bnrelu1_kernel<<<PTOT, 256>>>();
    convmma_kernel<<<dim3(PTOT / 128, 2), 256, SMEM_DYN>>>(out, x, 1);
}

// round 4
// speedup vs baseline: 6.9145x; 1.6348x over previous
#include <cuda_runtime.h>
#include <cuda_fp16.h>
#include <cstdint>

#define BB   32
#define CCH  256
#define HH   56
#define HWW  3136      // 56*56
#define HP   58        // padded spatial
#define PTOT 100352    // BB*HWW
#define WSZ  589824    // 256*256*9
#define WQN  294912    // u32 fragments per pass: 9*16*32*2*32

// ---------------- device scratch (zero-initialized .bss) ----------------
__device__ __align__(16) __half g_ah[BB * HP * HP * CCH];  // padded NHWC act, fp16 (borders stay 0)
__device__ __align__(16) __half g_out1h[(size_t)PTOT * CCH]; // conv1 output, NHWC fp16
__device__ __align__(16) uint32_t g_wq[2][WQN];            // sign(w) fp16x2, HMMA B-fragment order
__device__ float g_scale0[CCH], g_shift0[CCH];
__device__ float g_scale1[CCH], g_shift1[CCH];
__device__ float g_epart[128];
__device__ float g_E[2];
__device__ float g_ps[98 * CCH], g_pq[98 * CCH];

// ---------------- helpers ----------------
__device__ __forceinline__ uint32_t smem_u32(const void* p) {
    uint32_t a;
    asm("{ .reg .u64 t; cvta.to.shared.u64 t, %1; cvt.u32.u64 %0, t; }" : "=r"(a) : "l"(p));
    return a;
}
#define CPA16(dst, src) \
    asm volatile("cp.async.cg.shared.global [%0], [%1], 16;" :: "r"(dst), "l"(src) : "memory")
#define CPA_COMMIT() asm volatile("cp.async.commit_group;" ::: "memory")
#define CPA_WAIT(n)  asm volatile("cp.async.wait_group %0;" :: "n"(n) : "memory")

#define LDMATRIX_X4(r0, r1, r2, r3, addr) \
    asm volatile("ldmatrix.sync.aligned.m8n8.x4.shared.b16 {%0,%1,%2,%3}, [%4];" \
        : "=r"(r0), "=r"(r1), "=r"(r2), "=r"(r3) : "r"(addr))

#define MMA16816(c, a, b0, b1) \
    asm volatile("mma.sync.aligned.m16n8k16.row.col.f32.f16.f16.f32 " \
        "{%0,%1,%2,%3},{%4,%5,%6,%7},{%8,%9},{%0,%1,%2,%3};" \
        : "+f"((c)[0]), "+f"((c)[1]), "+f"((c)[2]), "+f"((c)[3]) \
        : "r"((a)[0]), "r"((a)[1]), "r"((a)[2]), "r"((a)[3]), "r"(b0), "r"(b1))

// ---------------- BN0 stats: one block per channel ----------------
__global__ void stats0_kernel(const float* __restrict__ x,
                              const float* __restrict__ gamma,
                              const float* __restrict__ beta)
{
    int c = blockIdx.x;
    int t = threadIdx.x;
    float s = 0.f, q = 0.f;
    for (int n = 0; n < BB; ++n) {
        const float* base = x + ((size_t)n * CCH + c) * HWW;
        for (int i = t; i < HWW; i += 256) {
            float v = base[i];
            s += v; q += v * v;
        }
    }
    __shared__ float ss[256], sq[256];
    ss[t] = s; sq[t] = q; __syncthreads();
    for (int o = 128; o > 0; o >>= 1) {
        if (t < o) { ss[t] += ss[t + o]; sq[t] += sq[t + o]; }
        __syncthreads();
    }
    if (t == 0) {
        float m   = ss[0] / (float)PTOT;
        float var = sq[0] / (float)PTOT - m * m;
        float sc  = gamma[c] * rsqrtf(var + 1e-5f);
        g_scale0[c] = sc;
        g_shift0[c] = beta[c] - m * sc;
    }
}

// ---------------- E = mean(|w|) ----------------
__global__ void eabs_part(const float* __restrict__ w0, const float* __restrict__ w1)
{
    int b = blockIdx.x;
    const float* w = (b < 64) ? w0 : w1;
    int bl = b & 63;
    int t = threadIdx.x;
    float s = 0.f;
    for (int i = bl * 256 + t; i < WSZ; i += 64 * 256) s += fabsf(w[i]);
    __shared__ float ss[256];
    ss[t] = s; __syncthreads();
    for (int o = 128; o > 0; o >>= 1) { if (t < o) ss[t] += ss[t + o]; __syncthreads(); }
    if (t == 0) g_epart[b] = ss[0];
}

__global__ void eabs_final()
{
    int t = threadIdx.x;
    if (t == 0) { float a = 0.f; for (int i = 0;  i < 64;  ++i) a += g_epart[i]; g_E[0] = a / (float)WSZ; }
    if (t == 1) { float a = 0.f; for (int i = 64; i < 128; ++i) a += g_epart[i]; g_E[1] = a / (float)WSZ; }
}

// ---------------- build sign(w) fp16 in HMMA B-fragment order ----------------
// layout: [tap 9][kstep 16][n8 32][reg 2][lane 32] as u32 = fp16x2 over (k, k+1)
// fragment semantics: k = kstep*16 + (lane&3)*2 + reg*8 (+0/+1), n(co) = n8*8 + (lane>>2)
__global__ void quantw_kernel(const float* __restrict__ w0, const float* __restrict__ w1)
{
    int idx = blockIdx.x * 256 + threadIdx.x;        // 0 .. 2*WQN
    int which = (idx >= WQN) ? 1 : 0;
    int i = idx - which * WQN;
    const float* w = which ? w1 : w0;
    int lane = i & 31;
    int r    = (i >> 5) & 1;
    int n8   = (i >> 6) & 31;
    int kst  = (i >> 11) & 15;
    int tap  = i >> 15;                               // 0..8
    int ci = kst * 16 + (lane & 3) * 2 + r * 8;
    int co = n8 * 8 + (lane >> 2);
    float v0 = w[co * 2304 + (ci + 0) * 9 + tap];     // OIHW source
    float v1 = w[co * 2304 + (ci + 1) * 9 + tap];
    uint32_t e0 = (v0 > 0.f) ? 0x3C00u : ((v0 < 0.f) ? 0xBC00u : 0u);  // +1/-1/0 fp16
    uint32_t e1 = (v1 > 0.f) ? 0x3C00u : ((v1 < 0.f) ? 0xBC00u : 0u);
    g_wq[which][i] = (e1 << 16) | e0;
}

// ---------------- BN0 + ReLU: NCHW -> padded NHWC fp16 ----------------
__global__ void bnrelu0_kernel(const float* __restrict__ x)
{
    __shared__ float sm[128][57];
    int h = blockIdx.x, n = blockIdx.y, cc = blockIdx.z;
    int t = threadIdx.x;
    #pragma unroll
    for (int it = 0; it < 28; ++it) {
        int idx = it * 256 + t;
        int cl = idx / 56, w = idx - cl * 56;
        sm[cl][w] = x[((size_t)(n * CCH + cc * 128 + cl)) * HWW + h * HH + w];
    }
    __syncthreads();
    int base = ((n * HP + h + 1) * HP + 1) * CCH + cc * 128;
    #pragma unroll
    for (int it = 0; it < 28; ++it) {
        int idx = it * 256 + t;
        int w = idx >> 7, cl = idx & 127;
        int c = cc * 128 + cl;
        float v = fmaxf(sm[cl][w] * g_scale0[c] + g_shift0[c], 0.f);
        g_ah[base + w * CCH + cl] = __float2half_rn(v);
    }
}

// ---------------- conv3x3 via mma.sync fp16: CTA 128px x 128co ----------------
// K = 9 taps x 256 ci. 36 stages (tap x 64-ci chunk).
// stage smem: A 16KB | B 16KB = 32KB, double-buffered. (pass-1 epilogue needs 67.6KB)
#define STG      32768
#define SMEM_DYN 69632

__global__ void __launch_bounds__(256, 2) convmma_kernel(float* __restrict__ dout,
                                                         const float* __restrict__ shortcut,
                                                         int pass)
{
    extern __shared__ __align__(16) char cs[];
    const int t    = threadIdx.x;
    const int lane = t & 31;
    const int wid  = t >> 5;
    const int wm   = wid & 3;          // M-warp (32 px)
    const int wn   = wid >> 2;         // N-warp (64 co)
    const int p0   = blockIdx.x * 128;
    const int bn   = blockIdx.y;       // co half
    const uint32_t sbase = smem_u32(cs);
    const uint32_t* __restrict__ wq = g_wq[pass];

    // loader mapping: thread -> row lr = t>>1, 64B half lh = t&1
    const int lr = t >> 1, lh = t & 1;
    const int lp = p0 + lr;
    const int ln = lp / HWW;
    const int ls = lp - ln * HWW;
    const int ly = ls / HH;
    const int lx = ls - ly * HH;
    const uint32_t labase = ((uint32_t)(ln * HP + ly) * HP + lx) * CCH;

#define LOAD_STAGE(M_, BUF_) do { \
        int tap_ = (M_) >> 2, ch_ = (M_) & 3; \
        int kh_ = tap_ / 3, kw_ = tap_ - kh_ * 3; \
        uint32_t aoff_ = labase + (uint32_t)(kh_ * HP + kw_) * CCH + ch_ * 64; \
        const char* sh_ = (const char*)(g_ah + aoff_); \
        uint32_t rowd_ = sbase + (BUF_) * STG + (uint32_t)lr * 128; \
        _Pragma("unroll") \
        for (int g_ = 0; g_ < 4; ++g_) { \
            int gg_ = lh * 4 + g_; \
            uint32_t sw_ = (uint32_t)((gg_ ^ (lr & 7)) << 4); \
            CPA16(rowd_ + sw_, sh_ + gg_ * 16); \
        } \
        _Pragma("unroll") \
        for (int j_ = 0; j_ < 4; ++j_) { \
            const char* bs_ = (const char*)(wq + (size_t)(tap_ * 16 + ch_ * 4 + j_) * 2048 + bn * 1024); \
            CPA16(sbase + (BUF_) * STG + 16384 + j_ * 4096 + t * 16, bs_ + t * 16); \
        } \
        CPA_COMMIT(); \
    } while (0)

    float acc[2][8][4];
    #pragma unroll
    for (int i = 0; i < 2; ++i)
        #pragma unroll
        for (int j = 0; j < 8; ++j)
            #pragma unroll
            for (int k = 0; k < 4; ++k) acc[i][j][k] = 0.f;

    LOAD_STAGE(0, 0);

    for (int m = 0; m < 36; ++m) {
        if (m + 1 < 36) { LOAD_STAGE(m + 1, (m + 1) & 1); CPA_WAIT(1); }
        else            { CPA_WAIT(0); }
        __syncthreads();

        const uint32_t Ab = sbase + (m & 1) * STG;
        #pragma unroll
        for (int ks = 0; ks < 4; ++ks) {
            uint32_t a[2][4];
            #pragma unroll
            for (int mt = 0; mt < 2; ++mt) {
                int row = wm * 32 + mt * 16 + (lane & 15);
                uint32_t addr = Ab + (uint32_t)row * 128
                              + (uint32_t)((((ks << 1) + (lane >> 4)) ^ (row & 7)) << 4);
                LDMATRIX_X4(a[mt][0], a[mt][1], a[mt][2], a[mt][3], addr);
            }
            #pragma unroll
            for (int nt = 0; nt < 8; ++nt) {
                int n8l = wn * 8 + nt;
                const uint32_t* bp = (const uint32_t*)(cs + ((m & 1) * STG + 16384)
                                    + (((ks * 16 + n8l) * 2) * 32 + lane) * 4);
                uint32_t b0 = bp[0];
                uint32_t b1 = bp[32];
                MMA16816(acc[0][nt], a[0], b0, b1);
                MMA16816(acc[1][nt], a[1], b0, b1);
            }
        }
        __syncthreads();
    }
#undef LOAD_STAGE

    const float E = g_E[pass];

    if (pass == 0) {
        // NHWC fp16 direct fragment stores (stats + conv2 both consume these values)
        #pragma unroll
        for (int mt = 0; mt < 2; ++mt) {
            int row0 = p0 + wm * 32 + mt * 16 + (lane >> 2);
            #pragma unroll
            for (int nt = 0; nt < 8; ++nt) {
                int co = bn * 128 + wn * 64 + nt * 8 + (lane & 3) * 2;
                __half2 v0 = __floats2half2_rn(acc[mt][nt][0] * E, acc[mt][nt][1] * E);
                __half2 v1 = __floats2half2_rn(acc[mt][nt][2] * E, acc[mt][nt][3] * E);
                *(__half2*)&g_out1h[(size_t)row0 * CCH + co]       = v0;
                *(__half2*)&g_out1h[(size_t)(row0 + 8) * CCH + co] = v1;
            }
        }
    } else {
        // transpose through smem, then coalesced NCHW stores + shortcut
        float* tsm = (float*)cs;   // [128 co][132]
        #pragma unroll
        for (int mt = 0; mt < 2; ++mt) {
            int r0 = wm * 32 + mt * 16 + (lane >> 2);
            #pragma unroll
            for (int nt = 0; nt < 8; ++nt) {
                int c = wn * 64 + nt * 8 + (lane & 3) * 2;
                tsm[(c + 0) * 132 + r0]     = acc[mt][nt][0];
                tsm[(c + 1) * 132 + r0]     = acc[mt][nt][1];
                tsm[(c + 0) * 132 + r0 + 8] = acc[mt][nt][2];
                tsm[(c + 1) * 132 + r0 + 8] = acc[mt][nt][3];
            }
        }
        __syncthreads();
        int p = p0 + lane * 4;
        int n = p / HWW;
        int s = p - n * HWW;
        #pragma unroll
        for (int cl = 0; cl < 16; ++cl) {
            int co = wid * 16 + cl;
            size_t oi = ((size_t)(n * CCH + bn * 128 + co)) * HWW + s;
            float4 sc = *(const float4*)&shortcut[oi];
            float4 v;
            v.x = tsm[co * 132 + lane * 4 + 0] * E + sc.x;
            v.y = tsm[co * 132 + lane * 4 + 1] * E + sc.y;
            v.z = tsm[co * 132 + lane * 4 + 2] * E + sc.z;
            v.w = tsm[co * 132 + lane * 4 + 3] * E + sc.w;
            *(float4*)&dout[oi] = v;
        }
    }
}

// ---------------- BN1 stats over g_out1h (NHWC fp16) ----------------
__global__ void stats1_part()
{
    int b = blockIdx.x, t = threadIdx.x;
    const __half* base = g_out1h + (size_t)b * 1024 * CCH;
    float s = 0.f, q = 0.f;
    for (int i = 0; i < 1024; ++i) {
        float v = __half2float(base[(size_t)i * CCH + t]);
        s += v; q += v * v;
    }
    g_ps[b * CCH + t] = s;
    g_pq[b * CCH + t] = q;
}

__global__ void stats1_final(const float* __restrict__ gamma, const float* __restrict__ beta)
{
    int c = threadIdx.x;
    float s = 0.f, q = 0.f;
    for (int b = 0; b < 98; ++b) { s += g_ps[b * CCH + c]; q += g_pq[b * CCH + c]; }
    float m   = s / (float)PTOT;
    float var = q / (float)PTOT - m * m;
    float sc  = gamma[c] * rsqrtf(var + 1e-5f);
    g_scale1[c] = sc;
    g_shift1[c] = beta[c] - m * sc;
}

// ---------------- BN1 + ReLU: NHWC fp16 -> padded NHWC fp16 ----------------
__global__ void bnrelu1_kernel()
{
    int p = blockIdx.x, t = threadIdx.x;
    int n = p / HWW, s = p - n * HWW;
    int y = s / HH, xw = s - y * HH;
    float v = __half2float(g_out1h[(size_t)p * CCH + t]);
    v = fmaxf(v * g_scale1[t] + g_shift1[t], 0.f);
    g_ah[((n * HP + y + 1) * HP + xw + 1) * CCH + t] = __float2half_rn(v);
}

// ---------------- launch ----------------
extern "C" void kernel_launch(void* const* d_in, const int* in_sizes, int n_in,
                              void* d_out, int out_size)
{
    const float* x      = (const float*)d_in[0];
    const float* gamma0 = (const float*)d_in[1];
    const float* beta0  = (const float*)d_in[2];
    const float* w0     = (const float*)d_in[3];
    const float* gamma1 = (const float*)d_in[4];
    const float* beta1  = (const float*)d_in[5];
    const float* w1     = (const float*)d_in[6];
    float* out = (float*)d_out;
    (void)in_sizes; (void)n_in; (void)out_size;

    static int smem_set = 0;
    if (!smem_set) {
        cudaFuncSetAttribute(convmma_kernel, cudaFuncAttributeMaxDynamicSharedMemorySize, SMEM_DYN);
        smem_set = 1;
    }

    stats0_kernel<<<256, 256>>>(x, gamma0, beta0);
    eabs_part<<<128, 256>>>(w0, w1);
    eabs_final<<<1, 32>>>();
    quantw_kernel<<<(2 * WQN) / 256, 256>>>(w0, w1);
    bnrelu0_kernel<<<dim3(HH, BB, 2), 256>>>(x);
    convmma_kernel<<<dim3(PTOT / 128, 2), 256, SMEM_DYN>>>(nullptr, nullptr, 0);
    stats1_part<<<98, 256>>>();
    stats1_final<<<1, 256>>>(gamma1, beta1);
    bnrelu1_kernel<<<PTOT, 256>>>();
    convmma_kernel<<<dim3(PTOT / 128, 2), 256, SMEM_DYN>>>(out, x, 1);
}